// round 7
// baseline (speedup 1.0000x reference)
#include <cuda_runtime.h>
#include <cuda.h>
#include <cuda_bf16.h>
#include <stdint.h>
#include <math.h>

typedef unsigned int u32;
typedef unsigned long long u64t;

// Fixed problem shape
#define NROWS 8192
#define DIM   128
#define BCLS  64
#define RBLK  128          // rows per block (one class per block)
#define CTILE 128          // cols per tile
#define NCHALF 2
#define CHALF (NROWS/NCHALF)           // 4096
#define NTILES (CHALF/CTILE)           // 32
#define NBUF  4

__device__ __align__(256) __nv_bfloat16 g_featb[NROWS * DIM];   // normalized, bf16
__device__ __align__(64) CUtensorMap g_mapF;                     // tensormap for g_featb
__device__ float g_all[NCHALF][2][NROWS];
__device__ float g_pos[NCHALF][2][NROWS];

// ---------------------------------------------------------------------------
// PTX helpers
// ---------------------------------------------------------------------------
__device__ __forceinline__ u32 smem_u32(const void* p) {
    return (u32)__cvta_generic_to_shared(p);
}
__device__ __forceinline__ void mbar_init(u32 addr, u32 cnt) {
    asm volatile("mbarrier.init.shared.b64 [%0], %1;" :: "r"(addr), "r"(cnt) : "memory");
}
__device__ __forceinline__ void mbar_expect(u32 addr, u32 bytes) {
    asm volatile("mbarrier.arrive.expect_tx.shared.b64 _, [%0], %1;"
                 :: "r"(addr), "r"(bytes) : "memory");
}
__device__ __forceinline__ void mbar_wait(u32 addr, u32 parity) {
    asm volatile("{\n\t.reg .pred P1;\n\t"
                 "WAIT_LP_%=:\n\t"
                 "mbarrier.try_wait.parity.acquire.cta.shared::cta.b64 P1, [%0], %1, 0x989680;\n\t"
                 "@P1 bra.uni WAIT_DN_%=;\n\t"
                 "bra.uni WAIT_LP_%=;\n\t"
                 "WAIT_DN_%=:\n\t}"
                 :: "r"(addr), "r"(parity) : "memory");
}
__device__ __forceinline__ void tma3d(u32 dst, const void* map, int cx, int cy, int cz,
                                      u32 mbar) {
    asm volatile("cp.async.bulk.tensor.3d.shared::cta.global.tile.mbarrier::complete_tx::bytes "
                 "[%0], [%1, {%2, %3, %4}], [%5];"
                 :: "r"(dst), "l"(map), "r"(cx), "r"(cy), "r"(cz), "r"(mbar) : "memory");
}
__device__ __forceinline__ void ldsm4(u32& q0, u32& q1, u32& q2, u32& q3, u32 addr) {
    asm volatile("ldmatrix.sync.aligned.m8n8.x4.shared.b16 {%0,%1,%2,%3}, [%4];"
                 : "=r"(q0), "=r"(q1), "=r"(q2), "=r"(q3) : "r"(addr));
}
__device__ __forceinline__ void mma16816(float* dacc, u32 qa0, u32 qa1,
                                         u32 qa2, u32 qa3, u32 qb0, u32 qb1) {
    asm volatile("mma.sync.aligned.m16n8k16.row.col.f32.bf16.bf16.f32 "
                 "{%0,%1,%2,%3}, {%4,%5,%6,%7}, {%8,%9}, {%0,%1,%2,%3};"
                 : "+f"(dacc[0]), "+f"(dacc[1]), "+f"(dacc[2]), "+f"(dacc[3])
                 : "r"(qa0), "r"(qa1), "r"(qa2), "r"(qa3), "r"(qb0), "r"(qb1));
}
__device__ __forceinline__ float ex2f(float v) {
    float r;
    asm("ex2.approx.f32 %0, %1;" : "=f"(r) : "f"(v));
    return r;
}

// ---------------------------------------------------------------------------
// Kernel 1: L2-normalize rows (fp32 math), emit bf16 [8192][128]
// ---------------------------------------------------------------------------
__global__ __launch_bounds__(256) void normalize_kernel(const float* __restrict__ x) {
    int gw   = (blockIdx.x * 256 + threadIdx.x) >> 5;
    int lane = threadIdx.x & 31;
    float4 v = ((const float4*)(x + (size_t)gw * DIM))[lane];
    float ss = v.x * v.x + v.y * v.y + v.z * v.z + v.w * v.w;
    #pragma unroll
    for (int o = 16; o; o >>= 1) ss += __shfl_xor_sync(0xffffffffu, ss, o);
    float inv = 1.0f / fmaxf(sqrtf(ss), 1e-12f);
    __nv_bfloat162 p0 = __floats2bfloat162_rn(v.x * inv, v.y * inv);
    __nv_bfloat162 p1 = __floats2bfloat162_rn(v.z * inv, v.w * inv);
    __nv_bfloat162* dst = (__nv_bfloat162*)(g_featb + (size_t)gw * DIM);
    dst[lane * 2 + 0] = p0;
    dst[lane * 2 + 1] = p1;
}

// ---------------------------------------------------------------------------
// Kernel 2: TMA + mma.sync fused sim + exp + masked row sums.
// Grid (2, 64): y = row block (128 rows, one class), x = column half (4096).
// 512 threads = 16 warps: rowgroup rg = w>>1 (16 rows), colgroup cg = w&1 (64 cols).
// SMEM: A tile 32KB (2x16KB halves) + 4 x 32KB B buffers. TMA SW128, 128B lines,
// line = tile row; halves (k 0..63 / 64..127) in separate 16KB regions.
// ---------------------------------------------------------------------------
__global__ __launch_bounds__(512) void fused_tma_kernel(const int* __restrict__ y) {
    extern __shared__ __align__(1024) char smem[];
    const u32 sA = smem_u32(smem);            // 32KB
    const u32 sB = sA + 32768;                // 4 x 32KB

    __shared__ __align__(8) u64t mbar_sh[NBUF];
    __shared__ int ys[BCLS];

    const int tid  = threadIdx.x;
    const int lane = tid & 31;
    const int w    = tid >> 5;
    const int rg   = w >> 1;                  // 0..7
    const int cg   = w & 1;                   // 0..1
    const int rowblk = blockIdx.y;
    const int chalf  = blockIdx.x;
    const int colrow0 = chalf * CHALF;        // feature-row index of first col
    const int myclass = __ldg(y + rowblk);

    u32 mb[NBUF];
    #pragma unroll
    for (int i = 0; i < NBUF; i++) mb[i] = smem_u32(&mbar_sh[i]);

    if (tid < BCLS) ys[tid] = y[tid];
    if (tid == 0) {
        #pragma unroll
        for (int i = 0; i < NBUF; i++) mbar_init(mb[i], 1);
    }
    __syncthreads();

    const CUtensorMap* mp = &g_mapF;
    if (tid == 0) {
        asm volatile("prefetch.tensormap [%0];" :: "l"(mp));
        // buf0: A (both halves) + B0 (both halves)
        mbar_expect(mb[0], 65536);
        tma3d(sA,          mp, 0, 0, rowblk * RBLK, mb[0]);
        tma3d(sA + 16384,  mp, 0, 1, rowblk * RBLK, mb[0]);
        tma3d(sB,          mp, 0, 0, colrow0,       mb[0]);
        tma3d(sB + 16384,  mp, 0, 1, colrow0,       mb[0]);
        // buf1, buf2
        mbar_expect(mb[1], 32768);
        tma3d(sB + 32768,  mp, 0, 0, colrow0 + CTILE, mb[1]);
        tma3d(sB + 49152,  mp, 0, 1, colrow0 + CTILE, mb[1]);
        mbar_expect(mb[2], 32768);
        tma3d(sB + 65536,  mp, 0, 0, colrow0 + 2 * CTILE, mb[2]);
        tma3d(sB + 81920,  mp, 0, 1, colrow0 + 2 * CTILE, mb[2]);
    }

    // float mask table: col%64 = p*16 + h*8 + 2*(lane&3) + b  (periodic, cg-free)
    float mf[4][2][2];
    #pragma unroll
    for (int p = 0; p < 4; p++) {
        #pragma unroll
        for (int h = 0; h < 2; h++) {
            int c0 = p * 16 + h * 8 + 2 * (lane & 3);
            mf[p][h][0] = (ys[c0]     == myclass) ? 1.0f : 0.0f;
            mf[p][h][1] = (ys[c0 + 1] == myclass) ? 1.0f : 0.0f;
        }
    }

    // ldmatrix addressing
    const int lr  = (lane & 7) | (((lane >> 3) & 1) << 3);  // row within 16
    const int hi  = lane >> 4;                               // 16B chunk parity
    const u32 swz = (u32)(lr & 7);
    const u32 rowA = (u32)((rg * 16 + lr) * 128);
    u32 rowB[4];
    #pragma unroll
    for (int p = 0; p < 4; p++) rowB[p] = (u32)((cg * 64 + p * 16 + lr) * 128);

    const float L2E = 1.4426950408889634f;
    float sa0 = 0.f, sa1 = 0.f, sp0 = 0.f, sp1 = 0.f;

    for (int t = 0; t < NTILES; t++) {
        mbar_wait(mb[t & 3], (u32)((t >> 2) & 1));
        const u32 bB = sB + (u32)((t & 3) * 32768);

        float acc[4][2][4];
        #pragma unroll
        for (int p = 0; p < 4; p++)
            #pragma unroll
            for (int h = 0; h < 2; h++)
                #pragma unroll
                for (int q = 0; q < 4; q++) acc[p][h][q] = 0.f;

        #pragma unroll
        for (int s = 0; s < 8; s++) {
            const u32 H   = (u32)((s >> 2) * 16384);
            const u32 off = ((u32)(2 * (s & 3) + hi) ^ swz) << 4;
            u32 qa0, qa1, qa2, qa3;
            ldsm4(qa0, qa1, qa2, qa3, sA + H + rowA + off);
            #pragma unroll
            for (int p = 0; p < 4; p++) {
                u32 qn0, qn1, qn2, qn3;
                ldsm4(qn0, qn1, qn2, qn3, bB + H + rowB[p] + off);
                mma16816(acc[p][0], qa0, qa1, qa2, qa3, qn0, qn2);
                mma16816(acc[p][1], qa0, qa1, qa2, qa3, qn1, qn3);
            }
        }

        // epilogue: e = exp(sim - 1) = ex2(sim*L2E - L2E); masked accumulate
        #pragma unroll
        for (int p = 0; p < 4; p++) {
            #pragma unroll
            for (int h = 0; h < 2; h++) {
                float e0 = ex2f(fmaf(acc[p][h][0], L2E, -L2E));
                float e1 = ex2f(fmaf(acc[p][h][1], L2E, -L2E));
                float e2 = ex2f(fmaf(acc[p][h][2], L2E, -L2E));
                float e3 = ex2f(fmaf(acc[p][h][3], L2E, -L2E));
                sa0 += e0 + e1;
                sa1 += e2 + e3;
                sp0 = fmaf(e0, mf[p][h][0], sp0);
                sp0 = fmaf(e1, mf[p][h][1], sp0);
                sp1 = fmaf(e2, mf[p][h][0], sp1);
                sp1 = fmaf(e3, mf[p][h][1], sp1);
            }
        }

        __syncthreads();   // all reads of buf[t&3]'s predecessor + current done
        if (tid == 0 && t + 3 < NTILES) {
            int tt = t + 3;
            u32 dst = sB + (u32)((tt & 3) * 32768);
            mbar_expect(mb[tt & 3], 32768);
            tma3d(dst,         mp, 0, 0, colrow0 + tt * CTILE, mb[tt & 3]);
            tma3d(dst + 16384, mp, 0, 1, colrow0 + tt * CTILE, mb[tt & 3]);
        }
    }

    // quad reduce (4 lanes share a row)
    #pragma unroll
    for (int o = 1; o <= 2; o <<= 1) {
        sa0 += __shfl_xor_sync(0xffffffffu, sa0, o);
        sa1 += __shfl_xor_sync(0xffffffffu, sa1, o);
        sp0 += __shfl_xor_sync(0xffffffffu, sp0, o);
        sp1 += __shfl_xor_sync(0xffffffffu, sp1, o);
    }
    if ((lane & 3) == 0) {
        int r = rowblk * RBLK + rg * 16 + (lane >> 2);
        g_all[chalf][cg][r]     = sa0;
        g_pos[chalf][cg][r]     = sp0;
        g_all[chalf][cg][r + 8] = sa1;
        g_pos[chalf][cg][r + 8] = sp1;
    }
}

// ---------------------------------------------------------------------------
// Kernel 3: per-row loss, deterministic tree reduce, mean.
// ---------------------------------------------------------------------------
__global__ __launch_bounds__(1024) void finalize_kernel(float* __restrict__ out) {
    __shared__ float red[1024];
    int t = threadIdx.x;
    float s = 0.f;
    #pragma unroll
    for (int i = 0; i < 8; i++) {
        int r = t * 8 + i;
        float all = g_all[0][0][r] + g_all[0][1][r] + g_all[1][0][r] + g_all[1][1][r];
        float pos = g_pos[0][0][r] + g_pos[0][1][r] + g_pos[1][0][r] + g_pos[1][1][r];
        s += -logf(pos / (all + 1e-8f) + 1e-8f);
    }
    red[t] = s;
    __syncthreads();
    #pragma unroll
    for (int o = 512; o; o >>= 1) {
        if (t < o) red[t] += red[t + o];
        __syncthreads();
    }
    if (t == 0) out[0] = red[0] / (float)NROWS;
}

// ---------------------------------------------------------------------------
// Host
// ---------------------------------------------------------------------------
typedef CUresult (*EncFn)(CUtensorMap*, CUtensorMapDataType, cuuint32_t, void*,
                          const cuuint64_t*, const cuuint64_t*, const cuuint32_t*,
                          const cuuint32_t*, CUtensorMapInterleave, CUtensorMapSwizzle,
                          CUtensorMapL2promotion, CUtensorMapFloatOOBfill);

extern "C" void kernel_launch(void* const* d_in, const int* in_sizes, int n_in,
                              void* d_out, int out_size) {
    const float* x = (const float*)d_in[0];   // [64,128,128] f32
    const int*   y = (const int*)d_in[1];     // [64] i32
    float* out = (float*)d_out;

    static CUtensorMap h_map;
    static int inited = 0;
    const int dyn_smem = (32 + NBUF * 32) * 1024;   // 160 KB
    if (!inited) {
        cudaFuncSetAttribute(fused_tma_kernel,
                             cudaFuncAttributeMaxDynamicSharedMemorySize, dyn_smem);
        void* fptr = 0;
        cudaDriverEntryPointQueryResult qr;
        cudaGetDriverEntryPoint("cuTensorMapEncodeTiled", &fptr,
                                cudaEnableDefault, &qr);
        void* dfeat = 0;
        cudaGetSymbolAddress(&dfeat, g_featb);
        // 3D view of g_featb: {64 bf16 (128B half-line), 2 halves, 8192 rows}
        cuuint64_t dims[3]    = {64, 2, NROWS};
        cuuint64_t strides[2] = {128, 256};           // bytes for dims 1,2
        cuuint32_t box[3]     = {64, 1, RBLK};        // 128B x 128 lines = 16KB
        cuuint32_t es[3]      = {1, 1, 1};
        ((EncFn)fptr)(&h_map, CU_TENSOR_MAP_DATA_TYPE_BFLOAT16, 3, dfeat,
                      dims, strides, box, es,
                      CU_TENSOR_MAP_INTERLEAVE_NONE, CU_TENSOR_MAP_SWIZZLE_128B,
                      CU_TENSOR_MAP_L2_PROMOTION_L2_128B,
                      CU_TENSOR_MAP_FLOAT_OOB_FILL_NONE);
        inited = 1;
    }

    cudaMemcpyToSymbolAsync(g_mapF, &h_map, sizeof(CUtensorMap), 0,
                            cudaMemcpyHostToDevice, 0);
    normalize_kernel<<<NROWS / 8, 256>>>(x);
    fused_tma_kernel<<<dim3(NCHALF, NROWS / RBLK), 512, dyn_smem>>>(y);
    finalize_kernel<<<1, 1024>>>(out);
}

// round 8
// speedup vs baseline: 1.0378x; 1.0378x over previous
#include <cuda_runtime.h>
#include <cuda.h>
#include <cuda_bf16.h>
#include <stdint.h>
#include <math.h>

typedef unsigned int u32;
typedef unsigned short u16;
typedef unsigned long long u64t;

// Fixed problem shape
#define NROWS 8192
#define DIM   128
#define BCLS  64
#define RBLK  128          // rows per block (one class per block)
#define CTILE 128          // cols per tile
#define NCHALF 2
#define CHALF (NROWS/NCHALF)           // 4096
#define NTILES (CHALF/CTILE)           // 32
#define NBUF  6
#define TILEB 16384        // fp8 tile bytes: 128 rows x 128B

__device__ __align__(256) unsigned char g_feat8[NROWS * DIM];   // normalized, e4m3
__device__ __align__(64) CUtensorMap g_mapF;
__device__ float g_all[NCHALF][2][NROWS];
__device__ float g_pos[NCHALF][2][NROWS];

// ---------------------------------------------------------------------------
// PTX helpers
// ---------------------------------------------------------------------------
__device__ __forceinline__ u32 smem_u32(const void* p) {
    return (u32)__cvta_generic_to_shared(p);
}
__device__ __forceinline__ void mbar_init(u32 addr, u32 cnt) {
    asm volatile("mbarrier.init.shared.b64 [%0], %1;" :: "r"(addr), "r"(cnt) : "memory");
}
__device__ __forceinline__ void mbar_expect(u32 addr, u32 bytes) {
    asm volatile("mbarrier.arrive.expect_tx.shared.b64 _, [%0], %1;"
                 :: "r"(addr), "r"(bytes) : "memory");
}
__device__ __forceinline__ void mbar_arrive(u32 addr) {
    asm volatile("mbarrier.arrive.shared.b64 _, [%0];" :: "r"(addr) : "memory");
}
__device__ __forceinline__ void mbar_wait(u32 addr, u32 parity) {
    asm volatile("{\n\t.reg .pred P1;\n\t"
                 "WAIT_LP_%=:\n\t"
                 "mbarrier.try_wait.parity.acquire.cta.shared::cta.b64 P1, [%0], %1, 0x989680;\n\t"
                 "@P1 bra.uni WAIT_DN_%=;\n\t"
                 "bra.uni WAIT_LP_%=;\n\t"
                 "WAIT_DN_%=:\n\t}"
                 :: "r"(addr), "r"(parity) : "memory");
}
__device__ __forceinline__ void tma2d(u32 dst, const void* map, int cx, int cy, u32 mbar) {
    asm volatile("cp.async.bulk.tensor.2d.shared::cta.global.tile.mbarrier::complete_tx::bytes "
                 "[%0], [%1, {%2, %3}], [%4];"
                 :: "r"(dst), "l"(map), "r"(cx), "r"(cy), "r"(mbar) : "memory");
}
__device__ __forceinline__ void ldsm4(u32& q0, u32& q1, u32& q2, u32& q3, u32 addr) {
    asm volatile("ldmatrix.sync.aligned.m8n8.x4.shared.b16 {%0,%1,%2,%3}, [%4];"
                 : "=r"(q0), "=r"(q1), "=r"(q2), "=r"(q3) : "r"(addr));
}
__device__ __forceinline__ void mma_fp8(float* dacc, u32 qa0, u32 qa1, u32 qa2, u32 qa3,
                                        u32 qb0, u32 qb1) {
    asm volatile("mma.sync.aligned.m16n8k32.row.col.f32.e4m3.e4m3.f32 "
                 "{%0,%1,%2,%3}, {%4,%5,%6,%7}, {%8,%9}, {%0,%1,%2,%3};"
                 : "+f"(dacc[0]), "+f"(dacc[1]), "+f"(dacc[2]), "+f"(dacc[3])
                 : "r"(qa0), "r"(qa1), "r"(qa2), "r"(qa3), "r"(qb0), "r"(qb1));
}
__device__ __forceinline__ float ex2f(float v) {
    float r;
    asm("ex2.approx.f32 %0, %1;" : "=f"(r) : "f"(v));
    return r;
}

// ---------------------------------------------------------------------------
// Kernel 1: L2-normalize rows (fp32 math), emit e4m3 [8192][128] (128B/row)
// One warp per row; lane handles 4 consecutive floats -> 4 fp8 bytes.
// ---------------------------------------------------------------------------
__global__ __launch_bounds__(256) void normalize_kernel(const float* __restrict__ x) {
    int gw   = (blockIdx.x * 256 + threadIdx.x) >> 5;
    int lane = threadIdx.x & 31;
    float4 v = ((const float4*)(x + (size_t)gw * DIM))[lane];
    float ss = v.x * v.x + v.y * v.y + v.z * v.z + v.w * v.w;
    #pragma unroll
    for (int o = 16; o; o >>= 1) ss += __shfl_xor_sync(0xffffffffu, ss, o);
    float inv = 1.0f / fmaxf(sqrtf(ss), 1e-12f);
    u16 p01, p23;
    asm("cvt.rn.satfinite.e4m3x2.f32 %0, %1, %2;" : "=h"(p01)
        : "f"(v.y * inv), "f"(v.x * inv));          // lo byte = x, hi = y
    asm("cvt.rn.satfinite.e4m3x2.f32 %0, %1, %2;" : "=h"(p23)
        : "f"(v.w * inv), "f"(v.z * inv));
    u32 word = (u32)p01 | ((u32)p23 << 16);
    ((u32*)(g_feat8 + (size_t)gw * DIM))[lane] = word;
}

// ---------------------------------------------------------------------------
// Kernel 2: TMA + fp8 mma.sync fused sim + exp + masked row sums.
// Grid (2, 64): y = row block (128 rows, one class), x = column half (4096).
// 512 threads = 16 warps: rg = w>>1 (16 rows), cg = w&1 (64 cols).
// SMEM: A 16KB + 6 x 16KB B ring. No __syncthreads in main loop: buffer
// release via per-buffer mbarrier (16 warp arrivals).
// ---------------------------------------------------------------------------
__global__ __launch_bounds__(512) void fused_fp8_kernel(const int* __restrict__ y) {
    extern __shared__ __align__(1024) char smem[];
    const u32 sA = smem_u32(smem);            // 16KB
    const u32 sB = sA + TILEB;                // 6 x 16KB ring

    __shared__ __align__(8) u64t full_sh[NBUF];
    __shared__ __align__(8) u64t rel_sh[NBUF];
    __shared__ int ys[BCLS];

    const int tid  = threadIdx.x;
    const int lane = tid & 31;
    const int w    = tid >> 5;
    const int rg   = w >> 1;                  // 0..7
    const int cg   = w & 1;                   // 0..1
    const int rowblk = blockIdx.y;
    const int chalf  = blockIdx.x;
    const int colrow0 = chalf * CHALF;
    const int myclass = __ldg(y + rowblk);

    u32 fullb[NBUF], relb[NBUF];
    #pragma unroll
    for (int i = 0; i < NBUF; i++) {
        fullb[i] = smem_u32(&full_sh[i]);
        relb[i]  = smem_u32(&rel_sh[i]);
    }

    if (tid < BCLS) ys[tid] = y[tid];
    if (tid == 0) {
        #pragma unroll
        for (int i = 0; i < NBUF; i++) { mbar_init(fullb[i], 1); mbar_init(relb[i], 16); }
    }
    __syncthreads();

    const CUtensorMap* mp = &g_mapF;
    if (tid == 0) {
        asm volatile("prefetch.tensormap [%0];" :: "l"(mp));
        // A + B0 share full[0]
        mbar_expect(fullb[0], 2 * TILEB);
        tma2d(sA, mp, 0, rowblk * RBLK, fullb[0]);
        tma2d(sB, mp, 0, colrow0, fullb[0]);
        #pragma unroll
        for (int b = 1; b < NBUF; b++) {
            mbar_expect(fullb[b], TILEB);
            tma2d(sB + (u32)(b * TILEB), mp, 0, colrow0 + b * CTILE, fullb[b]);
        }
    }

    // mask table: col%64 = nb*8 + 2*(lane&3) + bb  (cg*64 drops out mod 64)
    float mf[8][2];
    #pragma unroll
    for (int nb = 0; nb < 8; nb++) {
        int c0 = nb * 8 + 2 * (lane & 3);
        mf[nb][0] = (ys[c0]     == myclass) ? 1.0f : 0.0f;
        mf[nb][1] = (ys[c0 + 1] == myclass) ? 1.0f : 0.0f;
    }

    // ldmatrix addressing (fp8, 128B rows): lane -> row off = lane&15,
    // chunk = 2s + (lane>>4); addr = base + row*128 + ((chunk ^ (row&7))<<4)
    const int lrow = lane & 15;
    const u32 hi   = (u32)(lane >> 4);
    const int rA   = rg * 16 + lrow;
    const u32 offA = (u32)(rA * 128);
    const u32 swA  = (u32)(rA & 7);
    u32 offBp[4], swBp[4];
    #pragma unroll
    for (int pp = 0; pp < 4; pp++) {
        int rB = cg * 64 + pp * 16 + lrow;
        offBp[pp] = (u32)(rB * 128);
        swBp[pp]  = (u32)(rB & 7);
    }

    const float L2E = 1.4426950408889634f;
    float sa0 = 0.f, sa1 = 0.f, sp0 = 0.f, sp1 = 0.f;

    for (int t = 0; t < NTILES; t++) {
        const int b = t % NBUF;
        mbar_wait(fullb[b], (u32)((t / NBUF) & 1));
        const u32 bB = sB + (u32)(b * TILEB);

        float acc[8][4];
        #pragma unroll
        for (int nb = 0; nb < 8; nb++) {
            #pragma unroll
            for (int q = 0; q < 4; q++) acc[nb][q] = 0.f;
        }

        #pragma unroll
        for (int s = 0; s < 4; s++) {
            const u32 ch = (u32)(2 * s) + hi;
            u32 qa0, qa1, qa2, qa3;
            ldsm4(qa0, qa1, qa2, qa3, sA + offA + ((ch ^ swA) << 4));
            #pragma unroll
            for (int pp = 0; pp < 4; pp++) {
                u32 qb0, qb1, qb2, qb3;
                ldsm4(qb0, qb1, qb2, qb3, bB + offBp[pp] + ((ch ^ swBp[pp]) << 4));
                mma_fp8(acc[2 * pp],     qa0, qa1, qa2, qa3, qb0, qb2);
                mma_fp8(acc[2 * pp + 1], qa0, qa1, qa2, qa3, qb1, qb3);
            }
        }

        // done reading buffer b (epilogue uses registers only)
        if (lane == 0) mbar_arrive(relb[b]);

        // epilogue: e = exp(sim - 1) = ex2(sim*L2E - L2E); masked accumulate
        #pragma unroll
        for (int nb = 0; nb < 8; nb++) {
            float e0 = ex2f(fmaf(acc[nb][0], L2E, -L2E));
            float e1 = ex2f(fmaf(acc[nb][1], L2E, -L2E));
            float e2 = ex2f(fmaf(acc[nb][2], L2E, -L2E));
            float e3 = ex2f(fmaf(acc[nb][3], L2E, -L2E));
            sa0 += e0 + e1;
            sa1 += e2 + e3;
            sp0 = fmaf(e0, mf[nb][0], sp0);
            sp0 = fmaf(e1, mf[nb][1], sp0);
            sp1 = fmaf(e2, mf[nb][0], sp1);
            sp1 = fmaf(e3, mf[nb][1], sp1);
        }

        // producer: refill buffer b for tile t+NBUF once all 16 warps released it
        if (tid == 0 && t + NBUF < NTILES) {
            mbar_wait(relb[b], (u32)((t / NBUF) & 1));
            mbar_expect(fullb[b], TILEB);
            tma2d(sB + (u32)(b * TILEB), mp, 0, colrow0 + (t + NBUF) * CTILE, fullb[b]);
        }
    }

    // quad reduce (4 lanes share a row)
    #pragma unroll
    for (int o = 1; o <= 2; o <<= 1) {
        sa0 += __shfl_xor_sync(0xffffffffu, sa0, o);
        sa1 += __shfl_xor_sync(0xffffffffu, sa1, o);
        sp0 += __shfl_xor_sync(0xffffffffu, sp0, o);
        sp1 += __shfl_xor_sync(0xffffffffu, sp1, o);
    }
    if ((lane & 3) == 0) {
        int r = rowblk * RBLK + rg * 16 + (lane >> 2);
        g_all[chalf][cg][r]     = sa0;
        g_pos[chalf][cg][r]     = sp0;
        g_all[chalf][cg][r + 8] = sa1;
        g_pos[chalf][cg][r + 8] = sp1;
    }
}

// ---------------------------------------------------------------------------
// Kernel 3: per-row loss, deterministic tree reduce, mean.
// ---------------------------------------------------------------------------
__global__ __launch_bounds__(1024) void finalize_kernel(float* __restrict__ out) {
    __shared__ float red[1024];
    int t = threadIdx.x;
    float s = 0.f;
    #pragma unroll
    for (int i = 0; i < 8; i++) {
        int r = t * 8 + i;
        float all = g_all[0][0][r] + g_all[0][1][r] + g_all[1][0][r] + g_all[1][1][r];
        float pos = g_pos[0][0][r] + g_pos[0][1][r] + g_pos[1][0][r] + g_pos[1][1][r];
        s += -logf(pos / (all + 1e-8f) + 1e-8f);
    }
    red[t] = s;
    __syncthreads();
    #pragma unroll
    for (int o = 512; o; o >>= 1) {
        if (t < o) red[t] += red[t + o];
        __syncthreads();
    }
    if (t == 0) out[0] = red[0] / (float)NROWS;
}

// ---------------------------------------------------------------------------
// Host
// ---------------------------------------------------------------------------
typedef CUresult (*EncFn)(CUtensorMap*, CUtensorMapDataType, cuuint32_t, void*,
                          const cuuint64_t*, const cuuint64_t*, const cuuint32_t*,
                          const cuuint32_t*, CUtensorMapInterleave, CUtensorMapSwizzle,
                          CUtensorMapL2promotion, CUtensorMapFloatOOBfill);

extern "C" void kernel_launch(void* const* d_in, const int* in_sizes, int n_in,
                              void* d_out, int out_size) {
    const float* x = (const float*)d_in[0];   // [64,128,128] f32
    const int*   y = (const int*)d_in[1];     // [64] i32
    float* out = (float*)d_out;

    static CUtensorMap h_map;
    static int inited = 0;
    const int dyn_smem = (1 + NBUF) * TILEB;   // 112 KB
    if (!inited) {
        cudaFuncSetAttribute(fused_fp8_kernel,
                             cudaFuncAttributeMaxDynamicSharedMemorySize, dyn_smem);
        void* fptr = 0;
        cudaDriverEntryPointQueryResult qr;
        cudaGetDriverEntryPoint("cuTensorMapEncodeTiled", &fptr,
                                cudaEnableDefault, &qr);
        void* dfeat = 0;
        cudaGetSymbolAddress(&dfeat, g_feat8);
        // 2D view: {128 bytes, 8192 rows}, box {128, 128} = 16KB tile, SW128
        cuuint64_t dims[2]    = {DIM, NROWS};
        cuuint64_t strides[1] = {DIM};
        cuuint32_t box[2]     = {DIM, RBLK};
        cuuint32_t es[2]      = {1, 1};
        ((EncFn)fptr)(&h_map, CU_TENSOR_MAP_DATA_TYPE_UINT8, 2, dfeat,
                      dims, strides, box, es,
                      CU_TENSOR_MAP_INTERLEAVE_NONE, CU_TENSOR_MAP_SWIZZLE_128B,
                      CU_TENSOR_MAP_L2_PROMOTION_L2_128B,
                      CU_TENSOR_MAP_FLOAT_OOB_FILL_NONE);
        inited = 1;
    }

    cudaMemcpyToSymbolAsync(g_mapF, &h_map, sizeof(CUtensorMap), 0,
                            cudaMemcpyHostToDevice, 0);
    normalize_kernel<<<NROWS / 8, 256>>>(x);
    fused_fp8_kernel<<<dim3(NCHALF, NROWS / RBLK), 512, dyn_smem>>>(y);
    finalize_kernel<<<1, 1024>>>(out);
}